// round 14
// baseline (speedup 1.0000x reference)
#include <cuda_runtime.h>
#include <cuda_fp16.h>

#define Nn 100000
#define Ee 1600000
#define ETOT 1700000   // Ee + Nn self loops
#define NB 98          // ceil(Nn/1024)

// ---------------- scratch (device globals; no allocation) ----------------
__device__ int     g_count[Nn];
__device__ int     g_rowptr[Nn + 1];
__device__ int     g_wptr[Nn];
__device__ int     g_bsum[NB];
__device__ int     g_boff[NB];
__device__ int     g_src[ETOT];
__device__ __half2 g_feath[Nn * 32];   // transformed features (fp16, gather-only)
__device__ float   g_buf[Nn * 64];     // aggregated output (fp32, ping-pong)
__device__ float2  g_alsrc[Nn];        // per-node attention logits (src side)
__device__ float2  g_aldst[Nn];        // per-node attention logits (dst side)

__device__ __forceinline__ float lrelu(float x) { return fmaxf(x, 0.2f * x); }

// packed fp32x2 FMA (Blackwell; ptxas never emits it from C++)
__device__ __forceinline__ void ffma2(unsigned long long& d,
                                      unsigned long long a,
                                      unsigned long long b) {
    asm("fma.rn.f32x2 %0, %1, %2, %0;" : "+l"(d) : "l"(a), "l"(b));
}

// ---------------- CSR construction ----------------
__global__ void k_zero() {
    int i = blockIdx.x * blockDim.x + threadIdx.x;
    if (i < Nn) g_count[i] = 0;
}

__global__ void k_hist(const int* __restrict__ ei) {
    int i = blockIdx.x * blockDim.x + threadIdx.x;
    if (i >= ETOT) return;
    int d = (i < Ee) ? ei[Ee + i] : (i - Ee);
    atomicAdd(&g_count[d], 1);
}

__global__ void k_scan1() {
    __shared__ int s[1024];
    int t = threadIdx.x, i = blockIdx.x * 1024 + t;
    int v = (i < Nn) ? g_count[i] : 0;
    s[t] = v;
    __syncthreads();
    for (int o = 1; o < 1024; o <<= 1) {
        int a = (t >= o) ? s[t - o] : 0;
        __syncthreads();
        s[t] += a;
        __syncthreads();
    }
    if (i < Nn) g_rowptr[i + 1] = s[t];
    if (t == 1023) g_bsum[blockIdx.x] = s[t];
}

__global__ void k_scan2() {
    __shared__ int s[128];
    int t = threadIdx.x;
    s[t] = (t < NB) ? g_bsum[t] : 0;
    __syncthreads();
    for (int o = 1; o < 128; o <<= 1) {
        int a = (t >= o) ? s[t - o] : 0;
        __syncthreads();
        s[t] += a;
        __syncthreads();
    }
    if (t < NB) g_boff[t] = (t == 0) ? 0 : s[t - 1];
}

__global__ void k_scan3() {   // also produces g_wptr (= final rowptr)
    int t = threadIdx.x, i = blockIdx.x * 1024 + t;
    if (i < Nn) {
        int v = g_rowptr[i + 1] + g_boff[blockIdx.x];
        g_rowptr[i + 1] = v;
        if (i + 1 < Nn) g_wptr[i + 1] = v;
    }
    if (i == 0) { g_rowptr[0] = 0; g_wptr[0] = 0; }
}

__global__ void k_scatter(const int* __restrict__ ei) {
    int i = blockIdx.x * blockDim.x + threadIdx.x;
    if (i >= ETOT) return;
    int s, d;
    if (i < Ee) { s = ei[i]; d = ei[Ee + i]; }
    else        { s = d = i - Ee; }
    int pos = atomicAdd(&g_wptr[d], 1);
    g_src[pos] = s;
}

// ---------------- GEMM (8x4 tile, 256 thr, f32x2 FMA) + logit epilogue ------
// Block tile: 128 rows x 64 cols. Thread (cx = t&15, ry = t>>4) computes rows
// ry*8..+7, cols cx*4..+3. 16 u64 accumulators -> ~110 regs -> 2 blocks/SM.
template <int K, int HEADS, bool FROMX>
__global__ void __launch_bounds__(256) k_gemm(const float* __restrict__ Xp,
                                              const float* __restrict__ W,
                                              const float* __restrict__ av,
                                              const float* __restrict__ dv) {
    constexpr int KC  = 32;
    constexpr int STR = KC + 5;            // 37: conflict-free scalar LDS
    __shared__ float sX[128 * STR];        // 18944 B
    __shared__ float sW[KC * 64];          // 8192 B
    const float* X = FROMX ? Xp : g_buf;
    int t = threadIdx.x;
    int row0 = blockIdx.x * 128;
    int cx = t & 15;       // cols cx*4..cx*4+3
    int ry = t >> 4;       // rows ry*8..ry*8+7

    unsigned long long acc2[8][2];         // 8 rows x 2 col-pairs (4 cols)
#pragma unroll
    for (int i = 0; i < 8; i++) { acc2[i][0] = 0ull; acc2[i][1] = 0ull; }

    for (int k0 = 0; k0 < K; k0 += KC) {
        // X chunk (128 rows x 32 k): 1024 float4, 4 per thread
#pragma unroll
        for (int i = 0; i < 4; i++) {
            int idx = t + i * 256;
            int r = idx >> 3;
            int k4 = (idx & 7) << 2;
            int grow = row0 + r;
            float4 v = make_float4(0.f, 0.f, 0.f, 0.f);
            if (grow < Nn) v = *(const float4*)&X[(size_t)grow * K + k0 + k4];
            sX[r * STR + k4]     = v.x;
            sX[r * STR + k4 + 1] = v.y;
            sX[r * STR + k4 + 2] = v.z;
            sX[r * STR + k4 + 3] = v.w;
        }
        // W chunk (32 x 64): 512 float4, 2 per thread
#pragma unroll
        for (int i = 0; i < 2; i++) {
            int idx = t + i * 256;
            int k = idx >> 4;
            int c4 = (idx & 15) << 2;
            *(float4*)&sW[k * 64 + c4] = *(const float4*)&W[(size_t)(k0 + k) * 64 + c4];
        }
        __syncthreads();

#pragma unroll
        for (int k = 0; k < KC; k++) {
            ulonglong2 wv = *(const ulonglong2*)&sW[k * 64 + cx * 4];
#pragma unroll
            for (int i = 0; i < 8; i++) {
                unsigned xu = __float_as_uint(sX[(ry * 8 + i) * STR + k]);
                unsigned long long xp;
                asm("mov.b64 %0, {%1, %1};" : "=l"(xp) : "r"(xu));
                ffma2(acc2[i][0], xp, wv.x);
                ffma2(acc2[i][1], xp, wv.y);
            }
        }
        __syncthreads();
    }

    // epilogue: unpack, store feat (fp16) + per-row attention logits (fp32)
    float4 avA = *(const float4*)&av[cx * 4];
    float4 dvA = *(const float4*)&dv[cx * 4];

#pragma unroll
    for (int i = 0; i < 8; i++) {
        float a[4];
#pragma unroll
        for (int jp = 0; jp < 2; jp++) {
            unsigned lo, hi;
            asm("mov.b64 {%0, %1}, %2;" : "=r"(lo), "=r"(hi) : "l"(acc2[i][jp]));
            a[2 * jp]     = __uint_as_float(lo);
            a[2 * jp + 1] = __uint_as_float(hi);
        }
        int grow = row0 + ry * 8 + i;
        bool ok = (grow < Nn);
        if (ok) {
            __half2 h0 = __floats2half2_rn(a[0], a[1]);
            __half2 h1 = __floats2half2_rn(a[2], a[3]);
            uint2 pack;
            pack.x = *(unsigned*)&h0; pack.y = *(unsigned*)&h1;
            *(uint2*)&g_feath[(size_t)grow * 32 + cx * 2] = pack;
        }
        float ps = a[0] * avA.x + a[1] * avA.y + a[2] * avA.z + a[3] * avA.w;
        float pd = a[0] * dvA.x + a[1] * dvA.y + a[2] * dvA.z + a[3] * dvA.w;
        // reduce within 8-lane subgroup (cx 0-7 = head0 cols, cx 8-15 = head1)
        ps += __shfl_xor_sync(0xffffffffu, ps, 1);
        ps += __shfl_xor_sync(0xffffffffu, ps, 2);
        ps += __shfl_xor_sync(0xffffffffu, ps, 4);
        pd += __shfl_xor_sync(0xffffffffu, pd, 1);
        pd += __shfl_xor_sync(0xffffffffu, pd, 2);
        pd += __shfl_xor_sync(0xffffffffu, pd, 4);
        if (HEADS == 2) {
            float ps1 = __shfl_xor_sync(0xffffffffu, ps, 8);  // other head's sum
            float pd1 = __shfl_xor_sync(0xffffffffu, pd, 8);
            if (cx == 0 && ok) {
                g_alsrc[grow] = make_float2(ps, ps1);
                g_aldst[grow] = make_float2(pd, pd1);
            }
        } else {
            ps += __shfl_xor_sync(0xffffffffu, ps, 8);
            pd += __shfl_xor_sync(0xffffffffu, pd, 8);
            if (cx == 0 && ok) {
                g_alsrc[grow] = make_float2(ps, 0.f);
                g_aldst[grow] = make_float2(pd, 0.f);
            }
        }
    }
}

// ---------------- warp-per-dst: single-pass flash softmax, 4 subgroups ------
template <int HEADS, bool RELU, bool TOOUT>
__global__ void __launch_bounds__(256) k_edge(const float* __restrict__ bias,
                                              float* __restrict__ outp) {
    int w = (blockIdx.x * blockDim.x + threadIdx.x) >> 5;
    int lane = threadIdx.x & 31;
    if (w >= Nn) return;
    int beg = g_rowptr[w], end = g_rowptr[w + 1];

    int sub = lane >> 3;                  // 0..3: edge phase
    int q   = lane & 7;                   // channels 8q..8q+7
    bool hi = (HEADS == 2) && (q >= 4);   // channels >= 32 -> head 1
    float2 ad2 = g_aldst[w];
    float adh = hi ? ad2.y : ad2.x;

    const uint4* fh = (const uint4*)g_feath;   // 8 uint4 per row (64 ch)
    float m = -1e30f, d = 0.f;
    float a0 = 0.f, a1 = 0.f, a2 = 0.f, a3 = 0.f;
    float a4 = 0.f, a5 = 0.f, a6 = 0.f, a7 = 0.f;

    int e = beg + sub;
    for (; e + 4 < end; e += 8) {     // two edges: e, e+4
        int s0 = g_src[e], s1 = g_src[e + 4];
        float2 as0 = g_alsrc[s0];
        float2 as1 = g_alsrc[s1];
        uint4 u0 = fh[(size_t)s0 * 8 + q];
        uint4 u1 = fh[(size_t)s1 * 8 + q];
        float l0 = lrelu((hi ? as0.y : as0.x) + adh);
        float l1 = lrelu((hi ? as1.y : as1.x) + adh);
        float nm = fmaxf(m, fmaxf(l0, l1));
        float c  = __expf(m - nm);
        float p0 = __expf(l0 - nm);
        float p1 = __expf(l1 - nm);
        float2 f0 = __half22float2(*(__half2*)&u0.x);
        float2 f1 = __half22float2(*(__half2*)&u0.y);
        float2 f2 = __half22float2(*(__half2*)&u0.z);
        float2 f3 = __half22float2(*(__half2*)&u0.w);
        float2 g0 = __half22float2(*(__half2*)&u1.x);
        float2 g1 = __half22float2(*(__half2*)&u1.y);
        float2 g2 = __half22float2(*(__half2*)&u1.z);
        float2 g3 = __half22float2(*(__half2*)&u1.w);
        a0 = a0 * c + p0 * f0.x + p1 * g0.x;
        a1 = a1 * c + p0 * f0.y + p1 * g0.y;
        a2 = a2 * c + p0 * f1.x + p1 * g1.x;
        a3 = a3 * c + p0 * f1.y + p1 * g1.y;
        a4 = a4 * c + p0 * f2.x + p1 * g2.x;
        a5 = a5 * c + p0 * f2.y + p1 * g2.y;
        a6 = a6 * c + p0 * f3.x + p1 * g3.x;
        a7 = a7 * c + p0 * f3.y + p1 * g3.y;
        d  = d  * c + p0 + p1;
        m = nm;
    }
    if (e < end) {                    // at most one remaining edge
        int s0 = g_src[e];
        float2 as0 = g_alsrc[s0];
        uint4 u0 = fh[(size_t)s0 * 8 + q];
        float l0 = lrelu((hi ? as0.y : as0.x) + adh);
        float nm = fmaxf(m, l0);
        float c  = __expf(m - nm);
        float p0 = __expf(l0 - nm);
        float2 f0 = __half22float2(*(__half2*)&u0.x);
        float2 f1 = __half22float2(*(__half2*)&u0.y);
        float2 f2 = __half22float2(*(__half2*)&u0.z);
        float2 f3 = __half22float2(*(__half2*)&u0.w);
        a0 = a0 * c + p0 * f0.x;  a1 = a1 * c + p0 * f0.y;
        a2 = a2 * c + p0 * f1.x;  a3 = a3 * c + p0 * f1.y;
        a4 = a4 * c + p0 * f2.x;  a5 = a5 * c + p0 * f2.y;
        a6 = a6 * c + p0 * f3.x;  a7 = a7 * c + p0 * f3.y;
        d  = d  * c + p0;
        m = nm;
    }

    // merge 4 subgroups: stages 8, 16
#pragma unroll
    for (int st = 8; st <= 16; st <<= 1) {
        float mo = __shfl_xor_sync(0xffffffffu, m, st);
        float M  = fmaxf(m, mo);
        float c  = __expf(m - M);
        a0 *= c; a1 *= c; a2 *= c; a3 *= c;
        a4 *= c; a5 *= c; a6 *= c; a7 *= c;
        d *= c;
        a0 += __shfl_xor_sync(0xffffffffu, a0, st);
        a1 += __shfl_xor_sync(0xffffffffu, a1, st);
        a2 += __shfl_xor_sync(0xffffffffu, a2, st);
        a3 += __shfl_xor_sync(0xffffffffu, a3, st);
        a4 += __shfl_xor_sync(0xffffffffu, a4, st);
        a5 += __shfl_xor_sync(0xffffffffu, a5, st);
        a6 += __shfl_xor_sync(0xffffffffu, a6, st);
        a7 += __shfl_xor_sync(0xffffffffu, a7, st);
        d  += __shfl_xor_sync(0xffffffffu, d, st);
        m = M;
    }
    float inv = 1.f / d;

    if (lane < 8) {
        float4 b0 = ((const float4*)bias)[q * 2];
        float4 b1 = ((const float4*)bias)[q * 2 + 1];
        float4 r0, r1;
        r0.x = a0 * inv + b0.x; r0.y = a1 * inv + b0.y;
        r0.z = a2 * inv + b0.z; r0.w = a3 * inv + b0.w;
        r1.x = a4 * inv + b1.x; r1.y = a5 * inv + b1.y;
        r1.z = a6 * inv + b1.z; r1.w = a7 * inv + b1.w;
        if (RELU) {
            r0.x = fmaxf(r0.x, 0.f); r0.y = fmaxf(r0.y, 0.f);
            r0.z = fmaxf(r0.z, 0.f); r0.w = fmaxf(r0.w, 0.f);
            r1.x = fmaxf(r1.x, 0.f); r1.y = fmaxf(r1.y, 0.f);
            r1.z = fmaxf(r1.z, 0.f); r1.w = fmaxf(r1.w, 0.f);
        }
        float* dst = TOOUT ? outp : g_buf;
        ((float4*)dst)[(size_t)w * 16 + q * 2]     = r0;
        ((float4*)dst)[(size_t)w * 16 + q * 2 + 1] = r1;
    }
}

// ---------------- launch ----------------
extern "C" void kernel_launch(void* const* d_in, const int* in_sizes, int n_in,
                              void* d_out, int out_size) {
    const float* x   = (const float*)d_in[0];
    const int*   ei  = (const int*)d_in[1];
    const float* W1  = (const float*)d_in[2];
    const float* as1 = (const float*)d_in[3];
    const float* ad1 = (const float*)d_in[4];
    const float* b1  = (const float*)d_in[5];
    const float* W2  = (const float*)d_in[6];
    const float* as2 = (const float*)d_in[7];
    const float* ad2 = (const float*)d_in[8];
    const float* b2  = (const float*)d_in[9];
    const float* W3  = (const float*)d_in[10];
    const float* as3 = (const float*)d_in[11];
    const float* ad3 = (const float*)d_in[12];
    const float* b3  = (const float*)d_in[13];
    float* out = (float*)d_out;

    cudaStream_t sa;
    cudaEvent_t e0, e1;
    cudaStreamCreateWithFlags(&sa, cudaStreamNonBlocking);
    cudaEventCreateWithFlags(&e0, cudaEventDisableTiming);
    cudaEventCreateWithFlags(&e1, cudaEventDisableTiming);

    const int GB = (Nn + 127) / 128;       // GEMM blocks (128-row tiles)
    const int WG = (Nn * 32 + 255) / 256;  // one warp per node

    // fork: CSR build runs concurrently with layer-1 GEMM.
    cudaEventRecord(e0, 0);
    cudaStreamWaitEvent(sa, e0, 0);
    k_zero<<<(Nn + 255) / 256, 256, 0, sa>>>();                 // 1
    k_hist<<<(ETOT + 255) / 256, 256, 0, sa>>>(ei);             // 2
    k_scan1<<<NB, 1024, 0, sa>>>();                             // 3
    k_gemm<128, 2, true><<<GB, 256>>>(x, W1, as1, ad1);         // 4 <- profile target
    k_scan2<<<1, 128, 0, sa>>>();                               // 5
    k_scan3<<<NB, 1024, 0, sa>>>();                             // 6
    k_scatter<<<(ETOT + 255) / 256, 256, 0, sa>>>(ei);          // 7
    cudaEventRecord(e1, sa);

    cudaStreamWaitEvent(0, e1, 0);   // join: edge kernel needs CSR
    k_edge<2, true, false><<<WG, 256>>>(b1, nullptr);

    // layer 2: 64 -> 2x32, relu
    k_gemm<64, 2, false><<<GB, 256>>>(nullptr, W2, as2, ad2);
    k_edge<2, true, false><<<WG, 256>>>(b2, nullptr);

    // layer 3: 64 -> 1x64, no relu, write d_out
    k_gemm<64, 1, false><<<GB, 256>>>(nullptr, W3, as3, ad3);
    k_edge<1, false, true><<<WG, 256>>>(b3, out);
}

// round 15
// speedup vs baseline: 1.1592x; 1.1592x over previous
#include <cuda_runtime.h>
#include <cuda_fp16.h>

#define Nn 100000
#define Ee 1600000
#define ETOT 1700000   // Ee + Nn self loops
#define NB 98          // ceil(Nn/1024)

// ---------------- scratch (device globals; no allocation) ----------------
__device__ int     g_count[Nn];
__device__ int     g_rowptr[Nn + 1];
__device__ int     g_wptr[Nn];
__device__ int     g_bsum[NB];
__device__ int     g_boff[NB];
__device__ int     g_src[ETOT];
__device__ __half2 g_feath[Nn * 32];   // transformed features (fp16, gather-only)
__device__ float   g_buf[Nn * 64];     // aggregated output (fp32, ping-pong)
__device__ float2  g_alsrc[Nn];        // per-node attention logits (src side)
__device__ float2  g_aldst[Nn];        // per-node attention logits (dst side)

__device__ __forceinline__ float lrelu(float x) { return fmaxf(x, 0.2f * x); }

__device__ __forceinline__ void mma16816(float& c0, float& c1, float& c2, float& c3,
                                         unsigned a0, unsigned a1, unsigned a2, unsigned a3,
                                         unsigned b0, unsigned b1) {
    asm volatile(
        "mma.sync.aligned.m16n8k16.row.col.f32.f16.f16.f32 "
        "{%0,%1,%2,%3}, {%4,%5,%6,%7}, {%8,%9}, {%0,%1,%2,%3};"
        : "+f"(c0), "+f"(c1), "+f"(c2), "+f"(c3)
        : "r"(a0), "r"(a1), "r"(a2), "r"(a3), "r"(b0), "r"(b1));
}

// ---------------- CSR construction ----------------
__global__ void k_zero() {
    int i = blockIdx.x * blockDim.x + threadIdx.x;
    if (i < Nn) g_count[i] = 0;
}

__global__ void k_hist(const int* __restrict__ ei) {
    int i = blockIdx.x * blockDim.x + threadIdx.x;
    if (i >= ETOT) return;
    int d = (i < Ee) ? ei[Ee + i] : (i - Ee);
    atomicAdd(&g_count[d], 1);
}

__global__ void k_scan1() {
    __shared__ int s[1024];
    int t = threadIdx.x, i = blockIdx.x * 1024 + t;
    int v = (i < Nn) ? g_count[i] : 0;
    s[t] = v;
    __syncthreads();
    for (int o = 1; o < 1024; o <<= 1) {
        int a = (t >= o) ? s[t - o] : 0;
        __syncthreads();
        s[t] += a;
        __syncthreads();
    }
    if (i < Nn) g_rowptr[i + 1] = s[t];
    if (t == 1023) g_bsum[blockIdx.x] = s[t];
}

__global__ void k_scan2() {
    __shared__ int s[128];
    int t = threadIdx.x;
    s[t] = (t < NB) ? g_bsum[t] : 0;
    __syncthreads();
    for (int o = 1; o < 128; o <<= 1) {
        int a = (t >= o) ? s[t - o] : 0;
        __syncthreads();
        s[t] += a;
        __syncthreads();
    }
    if (t < NB) g_boff[t] = (t == 0) ? 0 : s[t - 1];
}

__global__ void k_scan3() {   // also produces g_wptr (= final rowptr)
    int t = threadIdx.x, i = blockIdx.x * 1024 + t;
    if (i < Nn) {
        int v = g_rowptr[i + 1] + g_boff[blockIdx.x];
        g_rowptr[i + 1] = v;
        if (i + 1 < Nn) g_wptr[i + 1] = v;
    }
    if (i == 0) { g_rowptr[0] = 0; g_wptr[0] = 0; }
}

__global__ void k_scatter(const int* __restrict__ ei) {
    int i = blockIdx.x * blockDim.x + threadIdx.x;
    if (i >= ETOT) return;
    int s, d;
    if (i < Ee) { s = ei[i]; d = ei[Ee + i]; }
    else        { s = d = i - Ee; }
    int pos = atomicAdd(&g_wptr[d], 1);
    g_src[pos] = s;
}

// ---------------- GEMM via HMMA (m16n8k16 fp16->fp32) + logit epilogue ------
// Block: 256 thr / 8 warps; tile 128 rows x 64 cols; K chunked by 64.
// Warp w owns rows w*16..+15; 8 n-tiles of 8 cols. Fragments loaded manually
// from padded smem (stride 72 halves -> conflict-free: word ≡ 4g+t mod 32).
template <int K, int HEADS, bool FROMX>
__global__ void __launch_bounds__(256) k_gemm(const float* __restrict__ Xp,
                                              const float* __restrict__ W,
                                              const float* __restrict__ av,
                                              const float* __restrict__ dv) {
    constexpr int KC   = 64;
    constexpr int STRH = KC + 8;            // 72 halves
    __shared__ __half sA[128 * STRH];       // 18432 B
    __shared__ __half sB[64 * STRH];        // 9216 B
    const float* X = FROMX ? Xp : g_buf;
    int t = threadIdx.x;
    int row0 = blockIdx.x * 128;
    int lane = t & 31;
    int wrow = (t >> 5) * 16;               // warp's first row in tile
    int g  = lane >> 2;                     // group id 0..7
    int tq = lane & 3;                      // quad thread 0..3

    float acc[8][4];
#pragma unroll
    for (int nt = 0; nt < 8; nt++)
#pragma unroll
        for (int j = 0; j < 4; j++) acc[nt][j] = 0.f;

    for (int k0 = 0; k0 < K; k0 += KC) {
        // A chunk: 128 rows x 64 k fp32 -> fp16 smem. 2048 float4, 8/thread.
#pragma unroll
        for (int i = 0; i < 8; i++) {
            int idx = t + i * 256;
            int r  = idx >> 4;
            int c4 = (idx & 15) << 2;
            int grow = row0 + r;
            float4 v = make_float4(0.f, 0.f, 0.f, 0.f);
            if (grow < Nn) v = *(const float4*)&X[(size_t)grow * K + k0 + c4];
            __half2 h0 = __floats2half2_rn(v.x, v.y);
            __half2 h1 = __floats2half2_rn(v.z, v.w);
            uint2 pk;
            pk.x = *(unsigned*)&h0; pk.y = *(unsigned*)&h1;
            *(uint2*)&sA[r * STRH + c4] = pk;
        }
        // W chunk: [64 k x 64 n] fp32 -> transposed fp16 sB[n][k]. 16/thread.
#pragma unroll
        for (int i = 0; i < 16; i++) {
            int idx = t + i * 256;
            int k = idx >> 6;
            int n = idx & 63;
            sB[n * STRH + k] = __float2half(W[(size_t)(k0 + k) * 64 + n]);
        }
        __syncthreads();

#pragma unroll
        for (int ks = 0; ks < KC; ks += 16) {
            unsigned a0 = *(const unsigned*)&sA[(wrow + g)     * STRH + ks + 2 * tq];
            unsigned a1 = *(const unsigned*)&sA[(wrow + g + 8) * STRH + ks + 2 * tq];
            unsigned a2 = *(const unsigned*)&sA[(wrow + g)     * STRH + ks + 2 * tq + 8];
            unsigned a3 = *(const unsigned*)&sA[(wrow + g + 8) * STRH + ks + 2 * tq + 8];
#pragma unroll
            for (int nt = 0; nt < 8; nt++) {
                unsigned b0 = *(const unsigned*)&sB[(nt * 8 + g) * STRH + ks + 2 * tq];
                unsigned b1 = *(const unsigned*)&sB[(nt * 8 + g) * STRH + ks + 2 * tq + 8];
                mma16816(acc[nt][0], acc[nt][1], acc[nt][2], acc[nt][3],
                         a0, a1, a2, a3, b0, b1);
            }
        }
        __syncthreads();
    }

    // epilogue. Lane holds rows r1 = row0+wrow+g (acc[nt][0..1]) and
    // r2 = r1+8 (acc[nt][2..3]); cols nt*8 + 2tq, +1.
    float avc[8][2], dvc[8][2];
#pragma unroll
    for (int nt = 0; nt < 8; nt++) {
        avc[nt][0] = av[nt * 8 + 2 * tq];
        avc[nt][1] = av[nt * 8 + 2 * tq + 1];
        dvc[nt][0] = dv[nt * 8 + 2 * tq];
        dvc[nt][1] = dv[nt * 8 + 2 * tq + 1];
    }

    int r1 = row0 + wrow + g;
    int r2 = r1 + 8;
    bool ok1 = (r1 < Nn), ok2 = (r2 < Nn);

    // feat stores (fp16 pairs)
#pragma unroll
    for (int nt = 0; nt < 8; nt++) {
        if (ok1) {
            __half2 h = __floats2half2_rn(acc[nt][0], acc[nt][1]);
            g_feath[(size_t)r1 * 32 + nt * 4 + tq] = h;
        }
        if (ok2) {
            __half2 h = __floats2half2_rn(acc[nt][2], acc[nt][3]);
            g_feath[(size_t)r2 * 32 + nt * 4 + tq] = h;
        }
    }

    // logits: head0 = tiles 0..3 (cols 0..31), head1 = tiles 4..7
    float s1h0 = 0.f, s1h1 = 0.f, d1h0 = 0.f, d1h1 = 0.f;
    float s2h0 = 0.f, s2h1 = 0.f, d2h0 = 0.f, d2h1 = 0.f;
#pragma unroll
    for (int nt = 0; nt < 4; nt++) {
        s1h0 += acc[nt][0] * avc[nt][0] + acc[nt][1] * avc[nt][1];
        d1h0 += acc[nt][0] * dvc[nt][0] + acc[nt][1] * dvc[nt][1];
        s2h0 += acc[nt][2] * avc[nt][0] + acc[nt][3] * avc[nt][1];
        d2h0 += acc[nt][2] * dvc[nt][0] + acc[nt][3] * dvc[nt][1];
    }
#pragma unroll
    for (int nt = 4; nt < 8; nt++) {
        s1h1 += acc[nt][0] * avc[nt][0] + acc[nt][1] * avc[nt][1];
        d1h1 += acc[nt][0] * dvc[nt][0] + acc[nt][1] * dvc[nt][1];
        s2h1 += acc[nt][2] * avc[nt][0] + acc[nt][3] * avc[nt][1];
        d2h1 += acc[nt][2] * dvc[nt][0] + acc[nt][3] * dvc[nt][1];
    }
    if (HEADS == 1) {   // single head spans all 64 cols
        s1h0 += s1h1; d1h0 += d1h1; s2h0 += s2h1; d2h0 += d2h1;
        s1h1 = d1h1 = s2h1 = d2h1 = 0.f;
    }
    // reduce across the 4 quad lanes (same rows)
#pragma unroll
    for (int o = 1; o <= 2; o <<= 1) {
        s1h0 += __shfl_xor_sync(0xffffffffu, s1h0, o);
        s1h1 += __shfl_xor_sync(0xffffffffu, s1h1, o);
        d1h0 += __shfl_xor_sync(0xffffffffu, d1h0, o);
        d1h1 += __shfl_xor_sync(0xffffffffu, d1h1, o);
        s2h0 += __shfl_xor_sync(0xffffffffu, s2h0, o);
        s2h1 += __shfl_xor_sync(0xffffffffu, s2h1, o);
        d2h0 += __shfl_xor_sync(0xffffffffu, d2h0, o);
        d2h1 += __shfl_xor_sync(0xffffffffu, d2h1, o);
    }
    if (tq == 0) {
        if (ok1) {
            g_alsrc[r1] = make_float2(s1h0, s1h1);
            g_aldst[r1] = make_float2(d1h0, d1h1);
        }
        if (ok2) {
            g_alsrc[r2] = make_float2(s2h0, s2h1);
            g_aldst[r2] = make_float2(d2h0, d2h1);
        }
    }
}

// ---------------- warp-per-dst: single-pass flash softmax, 4 subgroups ------
template <int HEADS, bool RELU, bool TOOUT>
__global__ void __launch_bounds__(256) k_edge(const float* __restrict__ bias,
                                              float* __restrict__ outp) {
    int w = (blockIdx.x * blockDim.x + threadIdx.x) >> 5;
    int lane = threadIdx.x & 31;
    if (w >= Nn) return;
    int beg = g_rowptr[w], end = g_rowptr[w + 1];

    int sub = lane >> 3;                  // 0..3: edge phase
    int q   = lane & 7;                   // channels 8q..8q+7
    bool hi = (HEADS == 2) && (q >= 4);   // channels >= 32 -> head 1
    float2 ad2 = g_aldst[w];
    float adh = hi ? ad2.y : ad2.x;

    const uint4* fh = (const uint4*)g_feath;   // 8 uint4 per row (64 ch)
    float m = -1e30f, d = 0.f;
    float a0 = 0.f, a1 = 0.f, a2 = 0.f, a3 = 0.f;
    float a4 = 0.f, a5 = 0.f, a6 = 0.f, a7 = 0.f;

    int e = beg + sub;
    for (; e + 4 < end; e += 8) {     // two edges: e, e+4
        int s0 = g_src[e], s1 = g_src[e + 4];
        float2 as0 = g_alsrc[s0];
        float2 as1 = g_alsrc[s1];
        uint4 u0 = fh[(size_t)s0 * 8 + q];
        uint4 u1 = fh[(size_t)s1 * 8 + q];
        float l0 = lrelu((hi ? as0.y : as0.x) + adh);
        float l1 = lrelu((hi ? as1.y : as1.x) + adh);
        float nm = fmaxf(m, fmaxf(l0, l1));
        float c  = __expf(m - nm);
        float p0 = __expf(l0 - nm);
        float p1 = __expf(l1 - nm);
        float2 f0 = __half22float2(*(__half2*)&u0.x);
        float2 f1 = __half22float2(*(__half2*)&u0.y);
        float2 f2 = __half22float2(*(__half2*)&u0.z);
        float2 f3 = __half22float2(*(__half2*)&u0.w);
        float2 g0 = __half22float2(*(__half2*)&u1.x);
        float2 g1 = __half22float2(*(__half2*)&u1.y);
        float2 g2 = __half22float2(*(__half2*)&u1.z);
        float2 g3 = __half22float2(*(__half2*)&u1.w);
        a0 = a0 * c + p0 * f0.x + p1 * g0.x;
        a1 = a1 * c + p0 * f0.y + p1 * g0.y;
        a2 = a2 * c + p0 * f1.x + p1 * g1.x;
        a3 = a3 * c + p0 * f1.y + p1 * g1.y;
        a4 = a4 * c + p0 * f2.x + p1 * g2.x;
        a5 = a5 * c + p0 * f2.y + p1 * g2.y;
        a6 = a6 * c + p0 * f3.x + p1 * g3.x;
        a7 = a7 * c + p0 * f3.y + p1 * g3.y;
        d  = d  * c + p0 + p1;
        m = nm;
    }
    if (e < end) {                    // at most one remaining edge
        int s0 = g_src[e];
        float2 as0 = g_alsrc[s0];
        uint4 u0 = fh[(size_t)s0 * 8 + q];
        float l0 = lrelu((hi ? as0.y : as0.x) + adh);
        float nm = fmaxf(m, l0);
        float c  = __expf(m - nm);
        float p0 = __expf(l0 - nm);
        float2 f0 = __half22float2(*(__half2*)&u0.x);
        float2 f1 = __half22float2(*(__half2*)&u0.y);
        float2 f2 = __half22float2(*(__half2*)&u0.z);
        float2 f3 = __half22float2(*(__half2*)&u0.w);
        a0 = a0 * c + p0 * f0.x;  a1 = a1 * c + p0 * f0.y;
        a2 = a2 * c + p0 * f1.x;  a3 = a3 * c + p0 * f1.y;
        a4 = a4 * c + p0 * f2.x;  a5 = a5 * c + p0 * f2.y;
        a6 = a6 * c + p0 * f3.x;  a7 = a7 * c + p0 * f3.y;
        d  = d  * c + p0;
        m = nm;
    }

    // merge 4 subgroups: stages 8, 16
#pragma unroll
    for (int st = 8; st <= 16; st <<= 1) {
        float mo = __shfl_xor_sync(0xffffffffu, m, st);
        float M  = fmaxf(m, mo);
        float c  = __expf(m - M);
        a0 *= c; a1 *= c; a2 *= c; a3 *= c;
        a4 *= c; a5 *= c; a6 *= c; a7 *= c;
        d *= c;
        a0 += __shfl_xor_sync(0xffffffffu, a0, st);
        a1 += __shfl_xor_sync(0xffffffffu, a1, st);
        a2 += __shfl_xor_sync(0xffffffffu, a2, st);
        a3 += __shfl_xor_sync(0xffffffffu, a3, st);
        a4 += __shfl_xor_sync(0xffffffffu, a4, st);
        a5 += __shfl_xor_sync(0xffffffffu, a5, st);
        a6 += __shfl_xor_sync(0xffffffffu, a6, st);
        a7 += __shfl_xor_sync(0xffffffffu, a7, st);
        d  += __shfl_xor_sync(0xffffffffu, d, st);
        m = M;
    }
    float inv = 1.f / d;

    if (lane < 8) {
        float4 b0 = ((const float4*)bias)[q * 2];
        float4 b1 = ((const float4*)bias)[q * 2 + 1];
        float4 r0, r1;
        r0.x = a0 * inv + b0.x; r0.y = a1 * inv + b0.y;
        r0.z = a2 * inv + b0.z; r0.w = a3 * inv + b0.w;
        r1.x = a4 * inv + b1.x; r1.y = a5 * inv + b1.y;
        r1.z = a6 * inv + b1.z; r1.w = a7 * inv + b1.w;
        if (RELU) {
            r0.x = fmaxf(r0.x, 0.f); r0.y = fmaxf(r0.y, 0.f);
            r0.z = fmaxf(r0.z, 0.f); r0.w = fmaxf(r0.w, 0.f);
            r1.x = fmaxf(r1.x, 0.f); r1.y = fmaxf(r1.y, 0.f);
            r1.z = fmaxf(r1.z, 0.f); r1.w = fmaxf(r1.w, 0.f);
        }
        float* dst = TOOUT ? outp : g_buf;
        ((float4*)dst)[(size_t)w * 16 + q * 2]     = r0;
        ((float4*)dst)[(size_t)w * 16 + q * 2 + 1] = r1;
    }
}

// ---------------- launch ----------------
extern "C" void kernel_launch(void* const* d_in, const int* in_sizes, int n_in,
                              void* d_out, int out_size) {
    const float* x   = (const float*)d_in[0];
    const int*   ei  = (const int*)d_in[1];
    const float* W1  = (const float*)d_in[2];
    const float* as1 = (const float*)d_in[3];
    const float* ad1 = (const float*)d_in[4];
    const float* b1  = (const float*)d_in[5];
    const float* W2  = (const float*)d_in[6];
    const float* as2 = (const float*)d_in[7];
    const float* ad2 = (const float*)d_in[8];
    const float* b2  = (const float*)d_in[9];
    const float* W3  = (const float*)d_in[10];
    const float* as3 = (const float*)d_in[11];
    const float* ad3 = (const float*)d_in[12];
    const float* b3  = (const float*)d_in[13];
    float* out = (float*)d_out;

    cudaStream_t sa;
    cudaEvent_t e0, e1;
    cudaStreamCreateWithFlags(&sa, cudaStreamNonBlocking);
    cudaEventCreateWithFlags(&e0, cudaEventDisableTiming);
    cudaEventCreateWithFlags(&e1, cudaEventDisableTiming);

    const int GB = (Nn + 127) / 128;       // GEMM blocks (128-row tiles)
    const int WG = (Nn * 32 + 255) / 256;  // one warp per node

    // fork: CSR build runs concurrently with layer-1 GEMM.
    cudaEventRecord(e0, 0);
    cudaStreamWaitEvent(sa, e0, 0);
    k_zero<<<(Nn + 255) / 256, 256, 0, sa>>>();                 // 1
    k_hist<<<(ETOT + 255) / 256, 256, 0, sa>>>(ei);             // 2
    k_scan1<<<NB, 1024, 0, sa>>>();                             // 3
    k_gemm<128, 2, true><<<GB, 256>>>(x, W1, as1, ad1);         // 4 <- profile target
    k_scan2<<<1, 128, 0, sa>>>();                               // 5
    k_scan3<<<NB, 1024, 0, sa>>>();                             // 6
    k_scatter<<<(ETOT + 255) / 256, 256, 0, sa>>>(ei);          // 7
    cudaEventRecord(e1, sa);

    cudaStreamWaitEvent(0, e1, 0);   // join: edge kernel needs CSR
    k_edge<2, true, false><<<WG, 256>>>(b1, nullptr);

    // layer 2: 64 -> 2x32, relu
    k_gemm<64, 2, false><<<GB, 256>>>(nullptr, W2, as2, ad2);
    k_edge<2, true, false><<<WG, 256>>>(b2, nullptr);

    // layer 3: 64 -> 1x64, no relu, write d_out
    k_gemm<64, 1, false><<<GB, 256>>>(nullptr, W3, as3, ad3);
    k_edge<1, false, true><<<WG, 256>>>(b3, out);
}